// round 13
// baseline (speedup 1.0000x reference)
#include <cuda_runtime.h>
#include <cuda_fp16.h>
#include <cstdint>

// ---------------- problem constants ----------------
#define HID   4096
#define NEXP  4
#define RNK   8
#define MAXN  16384

// ---------------- GEMM tiling (fp16 operands) ----------------
#define BM 128
#define BN 256
#define BK 64                         // fp16 elements per K-chunk (128 bytes)
#define NCHUNK (HID / BK)             // 64
#define ROWB   144                    // 64 halves (128B) + 16B pad
#define A_ST   (BM * ROWB)            // 18432
#define B_ST   (BN * ROWB)            // 36864
#define STAGE_BYTES (A_ST + B_ST)     // 55296
#define STAGES 4
#define DYN_SMEM (STAGES * STAGE_BYTES)   // 221184
#define NTHREADS 288                  // 8 consumer warps + 1 producer warp

// scratch (allocation-free rule: __device__ globals live in bss)
__device__ float   g_zs[MAXN * RNK];
__device__ int     g_top1[MAXN];
__device__ __half  g_xh[(size_t)MAXN * HID];   // fp16 x   (128 MB)
__device__ __half  g_wh[(size_t)HID * HID];    // fp16 W   (32 MB)

// ---------------- PTX helpers ----------------
__device__ __forceinline__ uint32_t smem_u32(const void* p) {
    uint32_t a;
    asm("{ .reg .u64 t; cvta.to.shared.u64 t, %1; cvt.u32.u64 %0, t; }"
        : "=r"(a) : "l"(p));
    return a;
}
__device__ __forceinline__ void cp_async16(uint32_t dst, const void* src) {
    asm volatile("cp.async.cg.shared.global [%0], [%1], 16;"
                 :: "r"(dst), "l"(src) : "memory");
}
#define MBAR_INIT(a, c) \
    asm volatile("mbarrier.init.shared.b64 [%0], %1;" :: "r"(a), "r"(c) : "memory")
#define MBAR_ARRIVE(a) \
    asm volatile("mbarrier.arrive.shared.b64 _, [%0];" :: "r"(a) : "memory")
#define CPA_MBAR_ARRIVE(a) \
    asm volatile("cp.async.mbarrier.arrive.noinc.shared.b64 [%0];" :: "r"(a) : "memory")

__device__ __forceinline__ void mbar_wait(uint32_t addr, uint32_t parity) {
    asm volatile(
        "{\n\t.reg .pred P;\n\t"
        "W_%=:\n\t"
        "mbarrier.try_wait.parity.acquire.cta.shared::cta.b64 P, [%0], %1, 0x989680;\n\t"
        "@P bra.uni D_%=;\n\t"
        "bra.uni W_%=;\n\t"
        "D_%=:\n\t}"
        :: "r"(addr), "r"(parity) : "memory");
}

__device__ __forceinline__ void ldsm4(uint32_t* d, uint32_t addr) {
    asm volatile("ldmatrix.sync.aligned.m8n8.x4.shared.b16 {%0,%1,%2,%3}, [%4];"
                 : "=r"(d[0]), "=r"(d[1]), "=r"(d[2]), "=r"(d[3]) : "r"(addr));
}
__device__ __forceinline__ uint32_t pack_h2(float lo, float hi) {
    uint32_t r;
    asm("cvt.rn.f16x2.f32 %0, %1, %2;" : "=r"(r) : "f"(hi), "f"(lo));
    return r;
}
__device__ __forceinline__ void mma_f16(float* c, const uint32_t* a,
                                        uint32_t b0, uint32_t b1) {
    asm volatile(
        "mma.sync.aligned.m16n8k16.row.col.f32.f16.f16.f32 "
        "{%0,%1,%2,%3},{%4,%5,%6,%7},{%8,%9},{%0,%1,%2,%3};"
        : "+f"(c[0]), "+f"(c[1]), "+f"(c[2]), "+f"(c[3])
        : "r"(a[0]), "r"(a[1]), "r"(a[2]), "r"(a[3]), "r"(b0), "r"(b1));
}

// ---------------------------------------------------------------------------
// Kernel P: one-shot f32 -> fp16 pre-pass for W. x is converted in gate_z.
// ---------------------------------------------------------------------------
__global__ void cvt_f16_kernel(const float4* __restrict__ src,
                               uint4* __restrict__ dst, int n8) {
    for (int i = blockIdx.x * blockDim.x + threadIdx.x; i < n8;
         i += gridDim.x * blockDim.x) {
        float4 v0 = src[2 * i], v1 = src[2 * i + 1];
        uint4 o;
        o.x = pack_h2(v0.x, v0.y);
        o.y = pack_h2(v0.z, v0.w);
        o.z = pack_h2(v1.x, v1.y);
        o.w = pack_h2(v1.z, v1.w);
        dst[i] = o;
    }
}

// ---------------------------------------------------------------------------
// Kernel A: gating + LoRA z, x row cached in smem + fused f16(x) conversion
// ---------------------------------------------------------------------------
__global__ void gate_z_kernel(const float* __restrict__ x,
                              const float* __restrict__ gw,
                              const float* __restrict__ bias,
                              const float* __restrict__ lA) {
    const int n    = blockIdx.x;
    const int tid  = threadIdx.x;
    const int wid  = tid >> 5;
    const int lane = tid & 31;

    __shared__ float sx[HID];
    __shared__ float sred[4][RNK];
    __shared__ int   s_e;
    float4* sx4 = reinterpret_cast<float4*>(sx);

    const float4* xr = reinterpret_cast<const float4*>(x + (size_t)n * HID);
    uint2* xh2 = reinterpret_cast<uint2*>(g_xh + (size_t)n * HID);

    float a[NEXP] = {0.f, 0.f, 0.f, 0.f};
    const float4* gw4 = reinterpret_cast<const float4*>(gw);
    for (int h = tid; h < HID / 4; h += 128) {
        float4 xv = xr[h];
        sx4[h] = xv;
        uint2 o;
        o.x = pack_h2(xv.x, xv.y);
        o.y = pack_h2(xv.z, xv.w);
        xh2[h] = o;
#pragma unroll
        for (int e = 0; e < NEXP; e++) {
            float4 g = gw4[e * (HID / 4) + h];
            a[e] += xv.x * g.x + xv.y * g.y + xv.z * g.z + xv.w * g.w;
        }
    }
#pragma unroll
    for (int e = 0; e < NEXP; e++)
#pragma unroll
        for (int off = 16; off > 0; off >>= 1)
            a[e] += __shfl_xor_sync(0xffffffffu, a[e], off);
    if (lane == 0)
#pragma unroll
        for (int e = 0; e < NEXP; e++) sred[wid][e] = a[e];
    __syncthreads();
    if (tid == 0) {
        float best = -3.4e38f; int be = 0;
#pragma unroll
        for (int e = 0; e < NEXP; e++) {
            float v = sred[0][e] + sred[1][e] + sred[2][e] + sred[3][e] + bias[e];
            if (v > best) { best = v; be = e; }
        }
        s_e = be;
        g_top1[n] = be;
    }
    __syncthreads();

    const int e = s_e;
    const float4* A4 = reinterpret_cast<const float4*>(lA + (size_t)e * RNK * HID);
    float z[RNK];
#pragma unroll
    for (int r = 0; r < RNK; r++) z[r] = 0.f;
    for (int h = tid; h < HID / 4; h += 128) {
        float4 xv = sx4[h];
#pragma unroll
        for (int r = 0; r < RNK; r++) {
            float4 g = A4[r * (HID / 4) + h];
            z[r] += xv.x * g.x + xv.y * g.y + xv.z * g.z + xv.w * g.w;
        }
    }
#pragma unroll
    for (int r = 0; r < RNK; r++)
#pragma unroll
        for (int off = 16; off > 0; off >>= 1)
            z[r] += __shfl_xor_sync(0xffffffffu, z[r], off);
    __syncthreads();
    if (lane == 0)
#pragma unroll
        for (int r = 0; r < RNK; r++) sred[wid][r] = z[r];
    __syncthreads();
    if (tid < RNK)
        g_zs[(size_t)n * RNK + tid] =
            sred[0][tid] + sred[1][tid] + sred[2][tid] + sred[3][tid];
}

// ---------------------------------------------------------------------------
// Kernel B: warp-specialized fp16 GEMM. CTA 128x256x64, 8 consumer warps
// (warp grid 2m x 4n, 64x64 tiles) + 1 producer warp. 4-stage mbarrier ring.
// full[s]: 32 producer cp.async completions. empty[s]: 256 consumer arrivals.
// ---------------------------------------------------------------------------
__device__ __forceinline__ void load_chunk_p(uint32_t base,
                                             const __half* __restrict__ x,
                                             const __half* __restrict__ w,
                                             int m0, int n0, int k0, int lt) {
    const int seg = lt & 7;              // 16B segment in 128B row
    const int r0  = lt >> 3;             // 0..3
    const __half* ga = x + (size_t)(m0 + r0) * HID + k0 + seg * 8;
    const __half* gb = w + (size_t)(n0 + r0) * HID + k0 + seg * 8;
#pragma unroll 8
    for (int i = 0; i < 32; i++) {       // A: 128 rows
        const uint32_t off = (uint32_t)(r0 + i * 4) * ROWB + seg * 16;
        cp_async16(base + off, ga + (size_t)i * 4 * HID);
    }
#pragma unroll 8
    for (int i = 0; i < 64; i++) {       // B: 256 rows
        const uint32_t off = (uint32_t)(r0 + i * 4) * ROWB + seg * 16;
        cp_async16(base + A_ST + off, gb + (size_t)i * 4 * HID);
    }
}

__global__ __launch_bounds__(NTHREADS, 1)
void mma_gemm_kernel(const __half* __restrict__ x,
                     const __half* __restrict__ w,
                     const float* __restrict__ lB,
                     float* __restrict__ out) {
    extern __shared__ __align__(16) char dsm[];
    const uint32_t tiles = smem_u32(dsm);

    __shared__ __align__(8) unsigned long long s_bar[2 * STAGES];
    const uint32_t bfull  = smem_u32(s_bar);
    const uint32_t bempty = bfull + 8 * STAGES;

    const int tid  = threadIdx.x;
    const int wid  = tid >> 5;
    const int lane = tid & 31;
    const int m0   = blockIdx.y * BM;
    const int n0   = blockIdx.x * BN;

    if (tid == 0) {
#pragma unroll
        for (int s = 0; s < STAGES; s++) {
            MBAR_INIT(bfull  + 8 * s, 32);    // producer warp completions
            MBAR_INIT(bempty + 8 * s, 256);   // consumer arrivals
        }
    }
    __syncthreads();

    if (wid == 8) {
        // ================= PRODUCER WARP =================
        for (int k = 0; k < NCHUNK; k++) {
            const int s = k & 3, j = k >> 2;
            if (j >= 1) mbar_wait(bempty + 8 * s, (uint32_t)((j - 1) & 1));
            load_chunk_p(tiles + s * STAGE_BYTES, x, w, m0, n0, k * BK, lane);
            CPA_MBAR_ARRIVE(bfull + 8 * s);
        }
        return;   // producer exits; no epilogue work
    }

    // ================= CONSUMER WARPS (0..7) =================
    const int wm = (wid & 1) * 64;       // 2 warps in m
    const int wn = (wid >> 1) * 64;      // 4 warps in n

    uint32_t aoff[4];
#pragma unroll
    for (int mt = 0; mt < 4; mt++)
        aoff[mt] = (uint32_t)(wm + mt * 16 + (lane & 15)) * ROWB + (lane >> 4) * 16;
    uint32_t boff[8];
#pragma unroll
    for (int nt = 0; nt < 8; nt++)
        boff[nt] = (uint32_t)(A_ST + (wn + nt * 8 + (lane & 7)) * ROWB) + (lane >> 3) * 16;

    float c[4][8][4];
#pragma unroll
    for (int i = 0; i < 4; i++)
#pragma unroll
        for (int j = 0; j < 8; j++)
#pragma unroll
            for (int t = 0; t < 4; t++) c[i][j][t] = 0.f;

    uint32_t Bf[8][4], A0[4][4], A1[4][4];

#define CSLOT(S, PF)                                                           \
    {                                                                          \
        mbar_wait(bfull + 8 * (S), (PF));                                      \
        const uint32_t sbase = tiles + (S) * STAGE_BYTES;                      \
        _Pragma("unroll")                                                      \
        for (int nt = 0; nt < 8; nt++) ldsm4(Bf[nt], sbase + boff[nt]);        \
        _Pragma("unroll")                                                      \
        for (int mt = 0; mt < 4; mt++) ldsm4(A0[mt], sbase + aoff[mt]);        \
        _Pragma("unroll")                                                      \
        for (int mt = 0; mt < 4; mt++) ldsm4(A1[mt], sbase + aoff[mt] + 32);   \
        _Pragma("unroll")                                                      \
        for (int mt = 0; mt < 4; mt++)                                         \
            _Pragma("unroll")                                                  \
            for (int nt = 0; nt < 8; nt++)                                     \
                mma_f16(c[mt][nt], A0[mt], Bf[nt][0], Bf[nt][1]);              \
        _Pragma("unroll")                                                      \
        for (int mt = 0; mt < 4; mt++) ldsm4(A0[mt], sbase + aoff[mt] + 64);   \
        _Pragma("unroll")                                                      \
        for (int mt = 0; mt < 4; mt++)                                         \
            _Pragma("unroll")                                                  \
            for (int nt = 0; nt < 8; nt++)                                     \
                mma_f16(c[mt][nt], A1[mt], Bf[nt][2], Bf[nt][3]);              \
        _Pragma("unroll")                                                      \
        for (int nt = 0; nt < 8; nt++) ldsm4(Bf[nt], sbase + boff[nt] + 64);   \
        _Pragma("unroll")                                                      \
        for (int mt = 0; mt < 4; mt++) ldsm4(A1[mt], sbase + aoff[mt] + 96);   \
        MBAR_ARRIVE(bempty + 8 * (S));   /* all smem reads of stage S done */  \
        _Pragma("unroll")                                                      \
        for (int mt = 0; mt < 4; mt++)                                         \
            _Pragma("unroll")                                                  \
            for (int nt = 0; nt < 8; nt++)                                     \
                mma_f16(c[mt][nt], A0[mt], Bf[nt][0], Bf[nt][1]);              \
        _Pragma("unroll")                                                      \
        for (int mt = 0; mt < 4; mt++)                                         \
            _Pragma("unroll")                                                  \
            for (int nt = 0; nt < 8; nt++)                                     \
                mma_f16(c[mt][nt], A1[mt], Bf[nt][2], Bf[nt][3]);              \
    }

    for (int j = 0; j < NCHUNK / 4; j++) {     // 16 rounds x 4 stages
        const uint32_t pf = (uint32_t)(j & 1);
        CSLOT(0, pf);
        CSLOT(1, pf);
        CSLOT(2, pf);
        CSLOT(3, pf);
    }
#undef CSLOT

    // ---- epilogue: add LoRA delta, write out ----
    const int rowg = lane >> 2;
    const int colg = (lane & 3) * 2;
#pragma unroll
    for (int mt = 0; mt < 4; mt++) {
#pragma unroll
        for (int hr = 0; hr < 2; hr++) {
            const int row = m0 + wm + mt * 16 + hr * 8 + rowg;
            const int e   = g_top1[row];
            const float4* zz = reinterpret_cast<const float4*>(g_zs + (size_t)row * RNK);
            const float4 z0 = zz[0], z1 = zz[1];
            const float* lbe = lB + (size_t)e * HID * RNK;
            float* orow = out + (size_t)row * HID;
#pragma unroll
            for (int nt = 0; nt < 8; nt++) {
                const int col = n0 + wn + nt * 8 + colg;
                const float4* bp =
                    reinterpret_cast<const float4*>(lbe + (size_t)col * RNK);
                const float4 b0 = bp[0], b1 = bp[1];
                const float4* bq =
                    reinterpret_cast<const float4*>(lbe + (size_t)(col + 1) * RNK);
                const float4 q0 = bq[0], q1 = bq[1];
                float d0 = z0.x * b0.x + z0.y * b0.y + z0.z * b0.z + z0.w * b0.w
                         + z1.x * b1.x + z1.y * b1.y + z1.z * b1.z + z1.w * b1.w;
                float d1 = z0.x * q0.x + z0.y * q0.y + z0.z * q0.z + z0.w * q0.w
                         + z1.x * q1.x + z1.y * q1.y + z1.z * q1.z + z1.w * q1.w;
                float2 res = make_float2(c[mt][nt][hr * 2 + 0] + d0,
                                         c[mt][nt][hr * 2 + 1] + d1);
                *reinterpret_cast<float2*>(orow + col) = res;
            }
        }
    }
}

// ---------------------------------------------------------------------------
extern "C" void kernel_launch(void* const* d_in, const int* in_sizes, int n_in,
                              void* d_out, int out_size) {
    const float* x    = (const float*)d_in[0];
    const float* W_up = (const float*)d_in[1];
    const float* gw   = (const float*)d_in[2];
    const float* bias = (const float*)d_in[3];
    const float* lA   = (const float*)d_in[4];
    const float* lBm  = (const float*)d_in[5];
    float* out        = (float*)d_out;

    const int N = in_sizes[0] / HID;   // 16384 tokens

    cudaFuncSetAttribute(mma_gemm_kernel,
                         cudaFuncAttributeMaxDynamicSharedMemorySize, DYN_SMEM);
    cudaFuncSetAttribute(mma_gemm_kernel,
                         cudaFuncAttributePreferredSharedMemoryCarveout, 100);

    __half* xh = nullptr;
    __half* wh = nullptr;
    cudaGetSymbolAddress((void**)&xh, g_xh);
    cudaGetSymbolAddress((void**)&wh, g_wh);

    const int n8w = HID * HID / 8;
    cvt_f16_kernel<<<2048, 256>>>((const float4*)W_up, (uint4*)wh, n8w);

    gate_z_kernel<<<N, 128>>>(x, gw, bias, lA);

    dim3 grid(HID / BN, N / BM);       // (16, 128)
    mma_gemm_kernel<<<grid, NTHREADS, DYN_SMEM>>>(xh, wh, lBm, out);
}

// round 14
// speedup vs baseline: 1.6652x; 1.6652x over previous
#include <cuda_runtime.h>
#include <cuda_fp16.h>
#include <cstdint>

// ---------------- problem constants ----------------
#define HID   4096
#define NEXP  4
#define RNK   8
#define MAXN  16384
#define NOUT  36                      // 4 logits + 4 experts * rank 8

// ---------------- GEMM tiling (fp16 operands) ----------------
#define BM 128
#define BN 256
#define BK 64
#define NCHUNK (HID / BK)             // 64
#define ROWB   144
#define A_ST   (BM * ROWB)            // 18432
#define B_ST   (BN * ROWB)            // 36864
#define STAGE_BYTES (A_ST + B_ST)     // 55296
#define STAGES 3
#define DYN_SMEM (STAGES * STAGE_BYTES)   // 165888
#define NROUND ((NCHUNK + 2) / 3)     // 22

// ---------------- gate mini-GEMM tiling ----------------
#define GTOKB 128                     // tokens per block
#define KSPLIT 4                      // K split (1024 each)
#define GKC 64                        // k per chunk
#define GSX_W 129                     // padded token width for sx
#define GSX_BYTES (GKC * GSX_W * 4)   // 33024
#define GSW_BYTES (NOUT * GKC * 8)    // 18432 (float2 duplicated)
#define GATE_SMEM (GSX_BYTES + GSW_BYTES)

// scratch (allocation-free rule: __device__ globals live in bss)
__device__ float   g_zs[MAXN * RNK];
__device__ int     g_top1[MAXN];
__device__ float   g_zp[KSPLIT][MAXN][NOUT];   // gate partials (9.4 MB)
__device__ __half  g_xh[(size_t)MAXN * HID];   // fp16 x   (128 MB)
__device__ __half  g_wh[(size_t)HID * HID];    // fp16 W   (32 MB)

// ---------------- PTX helpers ----------------
__device__ __forceinline__ uint32_t smem_u32(const void* p) {
    uint32_t a;
    asm("{ .reg .u64 t; cvta.to.shared.u64 t, %1; cvt.u32.u64 %0, t; }"
        : "=r"(a) : "l"(p));
    return a;
}
__device__ __forceinline__ void cp_async16(uint32_t dst, const void* src) {
    asm volatile("cp.async.cg.shared.global [%0], [%1], 16;"
                 :: "r"(dst), "l"(src) : "memory");
}
#define MBAR_INIT(a, c) \
    asm volatile("mbarrier.init.shared.b64 [%0], %1;" :: "r"(a), "r"(c) : "memory")
#define MBAR_ARRIVE(a) \
    asm volatile("mbarrier.arrive.shared.b64 _, [%0];" :: "r"(a) : "memory")
#define CPA_MBAR_ARRIVE(a) \
    asm volatile("cp.async.mbarrier.arrive.noinc.shared.b64 [%0];" :: "r"(a) : "memory")

__device__ __forceinline__ void mbar_wait(uint32_t addr, uint32_t parity) {
    asm volatile(
        "{\n\t.reg .pred P;\n\t"
        "W_%=:\n\t"
        "mbarrier.try_wait.parity.acquire.cta.shared::cta.b64 P, [%0], %1, 0x989680;\n\t"
        "@P bra.uni D_%=;\n\t"
        "bra.uni W_%=;\n\t"
        "D_%=:\n\t}"
        :: "r"(addr), "r"(parity) : "memory");
}

__device__ __forceinline__ void ldsm4(uint32_t* d, uint32_t addr) {
    asm volatile("ldmatrix.sync.aligned.m8n8.x4.shared.b16 {%0,%1,%2,%3}, [%4];"
                 : "=r"(d[0]), "=r"(d[1]), "=r"(d[2]), "=r"(d[3]) : "r"(addr));
}
__device__ __forceinline__ uint32_t pack_h2(float lo, float hi) {
    uint32_t r;
    asm("cvt.rn.f16x2.f32 %0, %1, %2;" : "=r"(r) : "f"(hi), "f"(lo));
    return r;
}
__device__ __forceinline__ void mma_f16(float* c, const uint32_t* a,
                                        uint32_t b0, uint32_t b1) {
    asm volatile(
        "mma.sync.aligned.m16n8k16.row.col.f32.f16.f16.f32 "
        "{%0,%1,%2,%3},{%4,%5,%6,%7},{%8,%9},{%0,%1,%2,%3};"
        : "+f"(c[0]), "+f"(c[1]), "+f"(c[2]), "+f"(c[3])
        : "r"(a[0]), "r"(a[1]), "r"(a[2]), "r"(a[3]), "r"(b0), "r"(b1));
}
__device__ __forceinline__ unsigned long long pkf2(float lo, float hi) {
    unsigned long long r;
    asm("mov.b64 %0, {%1, %2};" : "=l"(r)
        : "r"(__float_as_uint(lo)), "r"(__float_as_uint(hi)));
    return r;
}
__device__ __forceinline__ void fma2(unsigned long long& c,
                                     unsigned long long a,
                                     unsigned long long b) {
    asm("fma.rn.f32x2 %0, %1, %2, %0;" : "+l"(c) : "l"(a), "l"(b));
}
__device__ __forceinline__ void upkf2(unsigned long long v, float& lo, float& hi) {
    unsigned int u0, u1;
    asm("mov.b64 {%0, %1}, %2;" : "=r"(u0), "=r"(u1) : "l"(v));
    lo = __uint_as_float(u0);
    hi = __uint_as_float(u1);
}

// ---------------------------------------------------------------------------
// Kernel P: one-shot f32 -> fp16 pre-pass for W.
// ---------------------------------------------------------------------------
__global__ void cvt_f16_kernel(const float4* __restrict__ src,
                               uint4* __restrict__ dst, int n8) {
    for (int i = blockIdx.x * blockDim.x + threadIdx.x; i < n8;
         i += gridDim.x * blockDim.x) {
        float4 v0 = src[2 * i], v1 = src[2 * i + 1];
        uint4 o;
        o.x = pack_h2(v0.x, v0.y);
        o.y = pack_h2(v0.z, v0.w);
        o.z = pack_h2(v1.x, v1.y);
        o.w = pack_h2(v1.z, v1.w);
        dst[i] = o;
    }
}

// ---------------------------------------------------------------------------
// Kernel G: all-expert gate mini-GEMM (fp32, f32x2) + fused f16(x) conversion.
// Z[token][36] = x . [gate_w ; lora_A]^T, K-split into KSPLIT partials.
// Block: 256 threads, 128 tokens, K range 1024. Grid: 512 blocks.
// Warp w: output group g = w&3 (9 outputs), token half h = w>>2.
// Thread: tokens (t, t+32) packed as an f32x2 lane pair.
// ---------------------------------------------------------------------------
__global__ __launch_bounds__(256)
void gate_gemm_kernel(const float* __restrict__ x,
                      const float* __restrict__ gw,
                      const float* __restrict__ lA) {
    extern __shared__ __align__(16) char gsm[];
    float*  sx  = reinterpret_cast<float*>(gsm);                 // [64][129]
    float2* sw2 = reinterpret_cast<float2*>(gsm + GSX_BYTES);    // [36][64]

    const int tid  = threadIdx.x;
    const int wid  = tid >> 5;
    const int lane = tid & 31;
    const int g    = wid & 3;           // output group: 9 outputs
    const int h    = wid >> 2;          // token half
    const int kidx = blockIdx.x & (KSPLIT - 1);
    const int T0   = (blockIdx.x >> 2) * GTOKB;
    const int K0   = kidx * (HID / KSPLIT);

    const int ta = h * 64 + lane;       // local token a (pairs with ta+32)

    unsigned long long c2[9];
#pragma unroll
    for (int i = 0; i < 9; i++) c2[i] = 0ull;

    for (int ch = 0; ch < (HID / KSPLIT) / GKC; ch++) {
        const int kc = K0 + ch * GKC;
        __syncthreads();
        // ---- load x tile [128 tok][64 k] + fused fp16 conversion ----
#pragma unroll
        for (int i = 0; i < 8; i++) {
            const int idx = tid + i * 256;         // 0..2047
            const int t   = idx >> 4;              // 0..127
            const int s   = idx & 15;              // float4 within 64-k row
            const float4 v = *reinterpret_cast<const float4*>(
                x + (size_t)(T0 + t) * HID + kc + s * 4);
            sx[(4 * s + 0) * GSX_W + t] = v.x;
            sx[(4 * s + 1) * GSX_W + t] = v.y;
            sx[(4 * s + 2) * GSX_W + t] = v.z;
            sx[(4 * s + 3) * GSX_W + t] = v.w;
            uint2 o;
            o.x = pack_h2(v.x, v.y);
            o.y = pack_h2(v.z, v.w);
            *reinterpret_cast<uint2*>(g_xh + (size_t)(T0 + t) * HID + kc + s * 4) = o;
        }
        // ---- load weight tile [36][64], duplicated for f32x2 ----
#pragma unroll
        for (int i = 0; i < 9; i++) {
            const int idx = tid + i * 256;         // 0..2303
            if (idx < NOUT * GKC) {
                const int o  = idx >> 6;           // 0..35
                const int kk = idx & 63;
                const float v = (o < NEXP)
                    ? gw[(size_t)o * HID + kc + kk]
                    : lA[(size_t)(o - NEXP) * HID + kc + kk];
                sw2[o * GKC + kk] = make_float2(v, v);
            }
        }
        __syncthreads();

        // ---- accumulate: 9 outputs x token-pair per thread ----
#pragma unroll 8
        for (int kk = 0; kk < GKC; kk++) {
            const float xa = sx[kk * GSX_W + ta];
            const float xb = sx[kk * GSX_W + ta + 32];
            const unsigned long long xp = pkf2(xa, xb);
            const float2* wrow = sw2 + kk;
#pragma unroll
            for (int i = 0; i < 9; i++) {
                const float2 wv = wrow[(g * 9 + i) * GKC];
                fma2(c2[i], xp, pkf2(wv.x, wv.y));
            }
        }
    }

    // ---- write partials ----
#pragma unroll
    for (int i = 0; i < 9; i++) {
        float va, vb;
        upkf2(c2[i], va, vb);
        g_zp[kidx][T0 + ta][g * 9 + i]      = va;
        g_zp[kidx][T0 + ta + 32][g * 9 + i] = vb;
    }
}

// ---------------------------------------------------------------------------
// Kernel S: combine K-split partials, argmax routing, select z.
// ---------------------------------------------------------------------------
__global__ void gate_select_kernel(const float* __restrict__ bias) {
    const int n = blockIdx.x * blockDim.x + threadIdx.x;
    float z[NOUT];
#pragma unroll
    for (int i = 0; i < NOUT; i++)
        z[i] = g_zp[0][n][i] + g_zp[1][n][i] + g_zp[2][n][i] + g_zp[3][n][i];
    float best = -3.4e38f; int be = 0;
#pragma unroll
    for (int e = 0; e < NEXP; e++) {
        const float v = z[e] + bias[e];
        if (v > best) { best = v; be = e; }
    }
    g_top1[n] = be;
#pragma unroll
    for (int r = 0; r < RNK; r++)
        g_zs[(size_t)n * RNK + r] = z[NEXP + be * RNK + r];
}

// ---------------------------------------------------------------------------
// Kernel B: fp16 GEMM (round-12 proven config). CTA 128x256x64, warp 64x64,
// 256 threads, 1 CTA/SM, 3-stage mbarrier producer/consumer ring.
// ---------------------------------------------------------------------------
__device__ __forceinline__ void load_chunk(uint32_t base,
                                           const __half* __restrict__ x,
                                           const __half* __restrict__ w,
                                           int m0, int n0, int k0, int tid) {
    const int seg = tid & 7;
    const int r0  = tid >> 3;
    const __half* ga = x + (size_t)(m0 + r0) * HID + k0 + seg * 8;
    const __half* gb = w + (size_t)(n0 + r0) * HID + k0 + seg * 8;
#pragma unroll
    for (int i = 0; i < 4; i++) {
        const uint32_t off = (uint32_t)(r0 + i * 32) * ROWB + seg * 16;
        cp_async16(base + off, ga + (size_t)i * 32 * HID);
    }
#pragma unroll
    for (int i = 0; i < 8; i++) {
        const uint32_t off = (uint32_t)(r0 + i * 32) * ROWB + seg * 16;
        cp_async16(base + A_ST + off, gb + (size_t)i * 32 * HID);
    }
}

__global__ __launch_bounds__(256, 1)
void mma_gemm_kernel(const __half* __restrict__ x,
                     const __half* __restrict__ w,
                     const float* __restrict__ lB,
                     float* __restrict__ out) {
    extern __shared__ __align__(16) char dsm[];
    const uint32_t tiles = smem_u32(dsm);

    __shared__ __align__(8) unsigned long long s_bar[2 * STAGES];
    const uint32_t bfull  = smem_u32(s_bar);
    const uint32_t bempty = bfull + 8 * STAGES;

    const int tid  = threadIdx.x;
    const int wid  = tid >> 5;
    const int lane = tid & 31;
    const int wm   = (wid & 1) * 64;
    const int wn   = (wid >> 1) * 64;
    const int m0   = blockIdx.y * BM;
    const int n0   = blockIdx.x * BN;

    uint32_t aoff[4];
#pragma unroll
    for (int mt = 0; mt < 4; mt++)
        aoff[mt] = (uint32_t)(wm + mt * 16 + (lane & 15)) * ROWB + (lane >> 4) * 16;
    uint32_t boff[8];
#pragma unroll
    for (int nt = 0; nt < 8; nt++)
        boff[nt] = (uint32_t)(A_ST + (wn + nt * 8 + (lane & 7)) * ROWB) + (lane >> 3) * 16;

    float c[4][8][4];
#pragma unroll
    for (int i = 0; i < 4; i++)
#pragma unroll
        for (int j = 0; j < 8; j++)
#pragma unroll
            for (int t = 0; t < 4; t++) c[i][j][t] = 0.f;

    if (tid == 0) {
#pragma unroll
        for (int s = 0; s < STAGES; s++) {
            MBAR_INIT(bfull  + 8 * s, 256);
            MBAR_INIT(bempty + 8 * s, 256);
        }
    }
    __syncthreads();

    load_chunk(tiles + 0 * STAGE_BYTES, x, w, m0, n0, 0 * BK, tid);
    CPA_MBAR_ARRIVE(bfull + 0);
    load_chunk(tiles + 1 * STAGE_BYTES, x, w, m0, n0, 1 * BK, tid);
    CPA_MBAR_ARRIVE(bfull + 8);

    uint32_t Bf[8][4], A0[4][4], A1[4][4];

#define SLOT(S, S2, PF, PE, DOWAIT, KK)                                        \
    if ((KK) < NCHUNK) {                                                       \
        mbar_wait(bfull + 8 * (S), (PF));                                      \
        const uint32_t sbase = tiles + (S) * STAGE_BYTES;                      \
        _Pragma("unroll")                                                      \
        for (int nt = 0; nt < 8; nt++) ldsm4(Bf[nt], sbase + boff[nt]);        \
        _Pragma("unroll")                                                      \
        for (int mt = 0; mt < 4; mt++) ldsm4(A0[mt], sbase + aoff[mt]);        \
        _Pragma("unroll")                                                      \
        for (int mt = 0; mt < 4; mt++) ldsm4(A1[mt], sbase + aoff[mt] + 32);   \
        _Pragma("unroll")                                                      \
        for (int mt = 0; mt < 4; mt++)                                         \
            _Pragma("unroll")                                                  \
            for (int nt = 0; nt < 8; nt++)                                     \
                mma_f16(c[mt][nt], A0[mt], Bf[nt][0], Bf[nt][1]);              \
        if ((KK) + 2 < NCHUNK) {                                               \
            if (DOWAIT) mbar_wait(bempty + 8 * (S2), (PE));                    \
            load_chunk(tiles + (S2) * STAGE_BYTES, x, w, m0, n0,               \
                       ((KK) + 2) * BK, tid);                                  \
            CPA_MBAR_ARRIVE(bfull + 8 * (S2));                                 \
        }                                                                      \
        _Pragma("unroll")                                                      \
        for (int mt = 0; mt < 4; mt++) ldsm4(A0[mt], sbase + aoff[mt] + 64);   \
        _Pragma("unroll")                                                      \
        for (int mt = 0; mt < 4; mt++)                                         \
            _Pragma("unroll")                                                  \
            for (int nt = 0; nt < 8; nt++)                                     \
                mma_f16(c[mt][nt], A1[mt], Bf[nt][2], Bf[nt][3]);              \
        _Pragma("unroll")                                                      \
        for (int nt = 0; nt < 8; nt++) ldsm4(Bf[nt], sbase + boff[nt] + 64);   \
        _Pragma("unroll")                                                      \
        for (int mt = 0; mt < 4; mt++) ldsm4(A1[mt], sbase + aoff[mt] + 96);   \
        _Pragma("unroll")                                                      \
        for (int mt = 0; mt < 4; mt++)                                         \
            _Pragma("unroll")                                                  \
            for (int nt = 0; nt < 8; nt++)                                     \
                mma_f16(c[mt][nt], A0[mt], Bf[nt][0], Bf[nt][1]);              \
        MBAR_ARRIVE(bempty + 8 * (S));                                         \
        _Pragma("unroll")                                                      \
        for (int mt = 0; mt < 4; mt++)                                         \
            _Pragma("unroll")                                                  \
            for (int nt = 0; nt < 8; nt++)                                     \
                mma_f16(c[mt][nt], A1[mt], Bf[nt][2], Bf[nt][3]);              \
    }

    for (int j = 0; j < NROUND; j++) {
        const uint32_t pf = (uint32_t)(j & 1);
        const uint32_t pm = (uint32_t)((j - 1) & 1);
        SLOT(0, 2, pf, pm, (j >= 1), 3 * j + 0);
        SLOT(1, 0, pf, pf, true,     3 * j + 1);
        SLOT(2, 1, pf, pf, true,     3 * j + 2);
    }
#undef SLOT

    // ---- epilogue: add LoRA delta, write out ----
    const int rowg = lane >> 2;
    const int colg = (lane & 3) * 2;
#pragma unroll
    for (int mt = 0; mt < 4; mt++) {
#pragma unroll
        for (int hr = 0; hr < 2; hr++) {
            const int row = m0 + wm + mt * 16 + hr * 8 + rowg;
            const int e   = g_top1[row];
            const float4* zz = reinterpret_cast<const float4*>(g_zs + (size_t)row * RNK);
            const float4 z0 = zz[0], z1 = zz[1];
            const float* lbe = lB + (size_t)e * HID * RNK;
            float* orow = out + (size_t)row * HID;
#pragma unroll
            for (int nt = 0; nt < 8; nt++) {
                const int col = n0 + wn + nt * 8 + colg;
                const float4* bp =
                    reinterpret_cast<const float4*>(lbe + (size_t)col * RNK);
                const float4 b0 = bp[0], b1 = bp[1];
                const float4* bq =
                    reinterpret_cast<const float4*>(lbe + (size_t)(col + 1) * RNK);
                const float4 q0 = bq[0], q1 = bq[1];
                float d0 = z0.x * b0.x + z0.y * b0.y + z0.z * b0.z + z0.w * b0.w
                         + z1.x * b1.x + z1.y * b1.y + z1.z * b1.z + z1.w * b1.w;
                float d1 = z0.x * q0.x + z0.y * q0.y + z0.z * q0.z + z0.w * q0.w
                         + z1.x * q1.x + z1.y * q1.y + z1.z * q1.z + z1.w * q1.w;
                float2 res = make_float2(c[mt][nt][hr * 2 + 0] + d0,
                                         c[mt][nt][hr * 2 + 1] + d1);
                *reinterpret_cast<float2*>(orow + col) = res;
            }
        }
    }
}

// ---------------------------------------------------------------------------
extern "C" void kernel_launch(void* const* d_in, const int* in_sizes, int n_in,
                              void* d_out, int out_size) {
    const float* x    = (const float*)d_in[0];
    const float* W_up = (const float*)d_in[1];
    const float* gw   = (const float*)d_in[2];
    const float* bias = (const float*)d_in[3];
    const float* lA   = (const float*)d_in[4];
    const float* lBm  = (const float*)d_in[5];
    float* out        = (float*)d_out;

    const int N = in_sizes[0] / HID;   // 16384 tokens

    cudaFuncSetAttribute(mma_gemm_kernel,
                         cudaFuncAttributeMaxDynamicSharedMemorySize, DYN_SMEM);
    cudaFuncSetAttribute(mma_gemm_kernel,
                         cudaFuncAttributePreferredSharedMemoryCarveout, 100);
    cudaFuncSetAttribute(gate_gemm_kernel,
                         cudaFuncAttributeMaxDynamicSharedMemorySize, GATE_SMEM);

    __half* xh = nullptr;
    __half* wh = nullptr;
    cudaGetSymbolAddress((void**)&xh, g_xh);
    cudaGetSymbolAddress((void**)&wh, g_wh);

    // gate mini-GEMM (also produces fp16 x), W conversion, routing select
    gate_gemm_kernel<<<(N / GTOKB) * KSPLIT, 256, GATE_SMEM>>>(x, gw, lA);
    cvt_f16_kernel<<<2048, 256>>>((const float4*)W_up, (uint4*)wh, HID * HID / 8);
    gate_select_kernel<<<N / 256, 256>>>(bias);

    dim3 grid(HID / BN, N / BM);       // (16, 128)
    mma_gemm_kernel<<<grid, 256, DYN_SMEM>>>(xh, wh, lBm, out);
}